// round 6
// baseline (speedup 1.0000x reference)
#include <cuda_runtime.h>
#include <cuda_fp16.h>
#include <cuda_bf16.h>
#include <cstdint>

#define BATCH 16
#define HW 409600
#define HW4 102400
#define PB 100          // blocks per batch in big passes
#define CHUNK4 1024     // float4 elems per block
#define NT 256
#define NKC 5
#define EPSL 1e-6

// ---------------- scratch (device globals; no runtime allocation) ----------
__device__ unsigned int g_hist1[BATCH][65536];   // 4 MB
__device__ unsigned int g_hist2[BATCH][65536];   // 4 MB
__device__ unsigned int g_negbits[BATCH * HW];   // 26 MB: p-bits of negatives, 0 otherwise
__device__ double g_sp[BATCH], g_sp2[BATCH], g_sp2_above[BATCH], g_losstext[BATCH];
__device__ unsigned int g_npos[BATCH], g_nneg[BATCH], g_B1[BATCH], g_cntA[BATCH], g_k[BATCH];
__device__ double g_ki[BATCH * NKC], g_kii[BATCH * NKC], g_ktt[BATCH * NKC];

// ---------------- helpers ----------------
// two sigmoids in one MUFU op: p = 0.5*tanh(x/2)+0.5 on f16x2
__device__ __forceinline__ __half2 htanh2(__half2 v) {
    unsigned u = *reinterpret_cast<unsigned*>(&v);
    unsigned r;
    asm("tanh.approx.f16x2 %0, %1;" : "=r"(r) : "r"(u));
    return *reinterpret_cast<__half2*>(&r);
}
__device__ __forceinline__ __half2 sig2(float x0, float x1) {
    const __half2 h05 = __half2half2(__float2half_rn(0.5f));
    __half2 h = __floats2half2_rn(x0, x1);   // one F2FP: h.x=x0, h.y=x1
    h = __hmul2(h, h05);                     // x/2
    __half2 t = htanh2(h);                   // one MUFU for 2 pixels
    return __hfma2(t, h05, h05);             // p = 0.5*t + 0.5
}

// packed f32x2 ops (sm_103a; ptxas will not auto-pack)
__device__ __forceinline__ unsigned long long pack2(float lo, float hi) {
    unsigned long long r;
    asm("mov.b64 %0, {%1, %2};" : "=l"(r) : "f"(lo), "f"(hi));
    return r;
}
__device__ __forceinline__ unsigned long long mul2(unsigned long long a, unsigned long long b) {
    unsigned long long r;
    asm("mul.rn.f32x2 %0, %1, %2;" : "=l"(r) : "l"(a), "l"(b));
    return r;
}
__device__ __forceinline__ unsigned long long fma2(unsigned long long a, unsigned long long b,
                                                   unsigned long long c) {
    unsigned long long r;
    asm("fma.rn.f32x2 %0, %1, %2, %3;" : "=l"(r) : "l"(a), "l"(b), "l"(c));
    return r;
}
__device__ __forceinline__ float hsum2(unsigned long long v) {
    float lo, hi;
    asm("mov.b64 {%0, %1}, %2;" : "=f"(lo), "=f"(hi) : "l"(v));
    return lo + hi;
}

// block reduce (result valid in thread 0); smem must hold >= 8 floats
__device__ __forceinline__ float blockReduceF(float v, float* s) {
    #pragma unroll
    for (int o = 16; o; o >>= 1) v += __shfl_down_sync(0xFFFFFFFFu, v, o);
    int lane = threadIdx.x & 31, w = threadIdx.x >> 5;
    if (lane == 0) s[w] = v;
    __syncthreads();
    v = (threadIdx.x < (blockDim.x >> 5)) ? s[threadIdx.x] : 0.0f;
    if (w == 0) {
        #pragma unroll
        for (int o = 4; o; o >>= 1) v += __shfl_down_sync(0xFFFFFFFFu, v, o);
    }
    __syncthreads();   // smem reusable after return
    return v;
}

// ---------------- kernels ----------------
__global__ void zero_kernel() {
    unsigned idx = blockIdx.x * blockDim.x + threadIdx.x;
    unsigned stride = gridDim.x * blockDim.x;
    const unsigned n = BATCH * 65536u;
    unsigned* h1 = &g_hist1[0][0];
    unsigned* h2 = &g_hist2[0][0];
    for (unsigned i = idx; i < n; i += stride) { h1[i] = 0u; h2[i] = 0u; }
    if (idx < BATCH) {
        g_sp[idx] = 0.0; g_sp2[idx] = 0.0; g_sp2_above[idx] = 0.0; g_losstext[idx] = 0.0;
        g_npos[idx] = 0u; g_nneg[idx] = 0u; g_B1[idx] = 0u; g_cntA[idx] = 0u; g_k[idx] = 0u;
    }
    if (idx < BATCH * NKC) { g_ki[idx] = 0.0; g_kii[idx] = 0.0; g_ktt[idx] = 0.0; }
}

__global__ void __launch_bounds__(NT) pass1_kernel(
    const float4* __restrict__ pred, const float4* __restrict__ gtt,
    const float4* __restrict__ gtk,  const float4* __restrict__ msk)
{
    __shared__ float sred[8];
    int b = blockIdx.x / PB;
    int base4 = (blockIdx.x % PB) * CHUNK4;

    const float4* m4 = msk + (size_t)b * HW4;
    const float4* g4 = gtt + (size_t)b * HW4;
    const float4* p4 = pred + (size_t)b * 6 * HW4;   // channel 0 = pred_text
    uint4* nb4 = reinterpret_cast<uint4*>(g_negbits) + (size_t)b * HW4;
    unsigned* __restrict__ h1 = &g_hist1[b][0];

    // packed masks held across the 5-channel loop
    unsigned long long m01[4], m23[4];
    float sp = 0.f, sp2 = 0.f, np = 0.f, nn = 0.f;

    #pragma unroll
    for (int i = 0; i < 4; i++) {
        int idx = base4 + threadIdx.x + i * NT;
        float4 mv = m4[idx];
        float4 gv = g4[idx];
        float4 pv = p4[idx];
        m01[i] = pack2(mv.x, mv.y);
        m23[i] = pack2(mv.z, mv.w);
        __half2 pA = sig2(pv.x, pv.y);
        __half2 pB = sig2(pv.z, pv.w);
        float ps0 = __low2float(pA), ps1 = __high2float(pA);
        float ps2 = __low2float(pB), ps3 = __high2float(pB);
        uint4 ob;
        // branchless pos-accumulation: pos = g*m (g,m are exact 0/1 floats)
        #define PROC(COMP, PV)                                                    \
        {                                                                         \
            float m = mv.COMP, g = gv.COMP;                                       \
            float p = PV;                                                         \
            unsigned bits = __float_as_uint(p);                                   \
            float pm = g * m;                                                     \
            float pp = p * pm;                                                    \
            np += pm; sp += pp; sp2 = fmaf(pp, pp, sp2);                          \
            unsigned o = 0u;                                                      \
            if (m - g > 0.5f) {       /* neg: m=1 && g=0 */                       \
                nn += 1.f; o = bits;                                              \
                atomicAdd(&h1[bits >> 16], 1u);                                   \
            }                                                                     \
            ob.COMP = o;                                                          \
        }
        PROC(x, ps0) PROC(y, ps1) PROC(z, ps2) PROC(w, ps3)
        #undef PROC
        nb4[idx] = ob;
    }

    float t;
    t = blockReduceF(sp,  sred); if (threadIdx.x == 0) atomicAdd(&g_sp[b],  (double)t);
    t = blockReduceF(sp2, sred); if (threadIdx.x == 0) atomicAdd(&g_sp2[b], (double)t);
    t = blockReduceF(np,  sred); if (threadIdx.x == 0) atomicAdd(&g_npos[b], (unsigned)(t + 0.5f));
    t = blockReduceF(nn,  sred); if (threadIdx.x == 0) atomicAdd(&g_nneg[b], (unsigned)(t + 0.5f));

    // kernel dice channels: branchless, f16x2 sigmoid + packed f32x2 accumulation
    // m,g in {0,1}:  sm = s*m;  sii += sm*s (= s^2 m);  int += sm*g (= s g m);  stt += g*m
    #pragma unroll 1
    for (int c = 0; c < NKC; c++) {
        const float4* pk = pred + ((size_t)b * 6 + 1 + c) * HW4;
        const float4* gk = gtk  + ((size_t)b * NKC + c) * HW4;
        unsigned long long sii01 = 0ull, sii23 = 0ull;
        unsigned long long int01 = 0ull, int23 = 0ull;
        unsigned long long stt01 = 0ull, stt23 = 0ull;
        #pragma unroll
        for (int i = 0; i < 4; i++) {
            int idx = base4 + threadIdx.x + i * NT;
            float4 pv = pk[idx];
            float4 gv = gk[idx];
            __half2 pA = sig2(pv.x, pv.y);
            __half2 pB = sig2(pv.z, pv.w);
            unsigned long long s01 = pack2(__low2float(pA), __high2float(pA));
            unsigned long long s23 = pack2(__low2float(pB), __high2float(pB));
            unsigned long long g01 = pack2(gv.x, gv.y);
            unsigned long long g23 = pack2(gv.z, gv.w);
            unsigned long long sm01 = mul2(s01, m01[i]);
            sii01 = fma2(sm01, s01, sii01);
            int01 = fma2(sm01, g01, int01);
            stt01 = fma2(g01, m01[i], stt01);
            unsigned long long sm23 = mul2(s23, m23[i]);
            sii23 = fma2(sm23, s23, sii23);
            int23 = fma2(sm23, g23, int23);
            stt23 = fma2(g23, m23[i], stt23);
        }
        int id = b * NKC + c;
        float r;
        r = blockReduceF(hsum2(int01) + hsum2(int23), sred);
        if (threadIdx.x == 0) atomicAdd(&g_ki[id],  (double)r);
        r = blockReduceF(hsum2(sii01) + hsum2(sii23), sred);
        if (threadIdx.x == 0) atomicAdd(&g_kii[id], (double)r);
        r = blockReduceF(hsum2(stt01) + hsum2(stt23), sred);
        if (threadIdx.x == 0) atomicAdd(&g_ktt[id], (double)r);
    }
}

// find high-16-bit bucket containing k-th largest negative score
__global__ void __launch_bounds__(1024) pass2_kernel() {
    int b = blockIdx.x;
    int t = threadIdx.x;
    __shared__ unsigned csum[1024];
    __shared__ unsigned suf[1024];
    __shared__ int sB1;
    __shared__ unsigned sCnt;

    unsigned npos = g_npos[b];
    unsigned nneg = g_nneg[b];
    unsigned k = 3u * npos; if (k > nneg) k = nneg;

    unsigned s = 0;
    #pragma unroll 8
    for (int j = 0; j < 64; j++) s += g_hist1[b][t * 64 + j];
    csum[t] = s;
    __syncthreads();
    if (t == 0) {
        unsigned acc = 0;
        for (int i = 1023; i >= 0; i--) { suf[i] = acc; acc += csum[i]; }
        sB1 = 0x7FFFFFFF;   // sentinel (k==0 case): never matched in pass3
        sCnt = 0u;
    }
    __syncthreads();
    if (k > 0) {
        unsigned before = suf[t];
        if (before < k && before + csum[t] >= k) {
            unsigned cum = before;
            for (int j = 63; j >= 0; j--) {
                unsigned c = g_hist1[b][t * 64 + j];
                if (cum + c >= k) { sB1 = t * 64 + j; sCnt = cum; break; }
                cum += c;
            }
        }
    }
    __syncthreads();
    if (t == 0) { g_k[b] = k; g_B1[b] = (unsigned)sB1; g_cntA[b] = sCnt; }
}

__global__ void __launch_bounds__(NT) pass3_kernel() {
    __shared__ float sred[8];
    int b = blockIdx.x / PB;
    int base4 = (blockIdx.x % PB) * CHUNK4;
    unsigned B1 = g_B1[b];
    const uint4* nb4 = reinterpret_cast<const uint4*>(g_negbits) + (size_t)b * HW4;

    float sp2a = 0.f;
    #pragma unroll
    for (int i = 0; i < 4; i++) {
        uint4 v = nb4[base4 + threadIdx.x + i * NT];
        #define PROC3(COMP)                                                       \
        {                                                                         \
            unsigned bits = v.COMP;                                               \
            if (bits) {                                                           \
                unsigned h = bits >> 16;                                          \
                if (h > B1) { float p = __uint_as_float(bits); sp2a += p * p; }   \
                else if (h == B1) atomicAdd(&g_hist2[b][bits & 0xFFFFu], 1u);     \
            }                                                                     \
        }
        PROC3(x) PROC3(y) PROC3(z) PROC3(w)
        #undef PROC3
    }
    float t = blockReduceF(sp2a, sred);
    if (threadIdx.x == 0) atomicAdd(&g_sp2_above[b], (double)t);
}

// resolve low 16 bits of threshold, exact hard-negative p^2 sum, per-batch text dice
__global__ void __launch_bounds__(1024) pass4_kernel() {
    int b = blockIdx.x;
    int t = threadIdx.x;
    __shared__ unsigned csum[1024];
    __shared__ unsigned suf[1024];
    __shared__ int sJ;
    __shared__ unsigned sCnt;
    __shared__ double dred[1024];

    unsigned k = g_k[b];
    unsigned cA = g_cntA[b];
    long long r = (long long)k - (long long)cA;
    unsigned B1 = g_B1[b];
    __shared__ double sHard;
    if (t == 0) sHard = g_sp2_above[b];

    if (r > 0) {
        unsigned s = 0;
        #pragma unroll 8
        for (int j = 0; j < 64; j++) s += g_hist2[b][t * 64 + j];
        csum[t] = s;
        __syncthreads();
        if (t == 0) {
            unsigned acc = 0;
            for (int i = 1023; i >= 0; i--) { suf[i] = acc; acc += csum[i]; }
            sJ = -1; sCnt = 0u;
        }
        __syncthreads();
        unsigned before = suf[t];
        if ((long long)before < r && (long long)(before + csum[t]) >= r) {
            unsigned cum = before;
            for (int j = 63; j >= 0; j--) {
                unsigned c = g_hist2[b][t * 64 + j];
                if ((long long)(cum + c) >= r) { sJ = t * 64 + j; sCnt = cum; break; }
                cum += c;
            }
        }
        __syncthreads();
        int jt = sJ;
        unsigned cAJ = sCnt;
        double ws = 0.0;
        for (int j = 0; j < 64; j++) {
            int gj = t * 64 + j;
            if (gj > jt) {
                unsigned c = g_hist2[b][gj];
                if (c) {
                    float v = __uint_as_float((B1 << 16) | (unsigned)gj);
                    ws += (double)c * (double)v * (double)v;
                }
            }
        }
        dred[t] = ws;
        __syncthreads();
        for (int o = 512; o; o >>= 1) {
            if (t < o) dred[t] += dred[t + o];
            __syncthreads();
        }
        if (t == 0) {
            float vt = __uint_as_float((B1 << 16) | (unsigned)jt);
            sHard += dred[0] + (double)(r - (long long)cAJ) * (double)vt * (double)vt;
        }
        __syncthreads();
    }
    if (t == 0) {
        double np = (double)g_npos[b];
        g_losstext[b] = 1.0 - 2.0 * g_sp[b] / (g_sp2[b] + sHard + np + EPSL);
    }
}

__global__ void final_kernel(float* out) {
    if (threadIdx.x == 0) {
        double lk = 0.0;
        for (int i = 0; i < BATCH * NKC; i++)
            lk += 1.0 - 2.0 * g_ki[i] / (g_kii[i] + g_ktt[i] + EPSL);
        lk /= (double)(BATCH * NKC);
        double lt = 0.0;
        for (int bb = 0; bb < BATCH; bb++) lt += g_losstext[bb];
        lt /= (double)BATCH;
        out[0] = (float)(lk + 0.5 * lt);
        out[1] = (float)lt;
        out[2] = (float)lk;
    }
}

// ---------------- launch ----------------
extern "C" void kernel_launch(void* const* d_in, const int* in_sizes, int n_in,
                              void* d_out, int out_size) {
    const float4* pred = (const float4*)d_in[0];
    const float4* gtt  = (const float4*)d_in[1];
    const float4* gtk  = (const float4*)d_in[2];
    const float4* msk  = (const float4*)d_in[3];
    float* out = (float*)d_out;

    zero_kernel<<<1024, 1024>>>();
    pass1_kernel<<<BATCH * PB, NT>>>(pred, gtt, gtk, msk);
    pass2_kernel<<<BATCH, 1024>>>();
    pass3_kernel<<<BATCH * PB, NT>>>();
    pass4_kernel<<<BATCH, 1024>>>();
    final_kernel<<<1, 32>>>(out);
}

// round 7
// speedup vs baseline: 2.5726x; 2.5726x over previous
#include <cuda_runtime.h>
#include <cuda_fp16.h>
#include <cuda_bf16.h>
#include <cstdint>

#define BATCH 16
#define HW 409600
#define HW4 102400
#define PB 100          // blocks per batch in pass1
#define CHUNK4 1024     // float4 elems per block
#define NT 256
#define NKC 5
#define EPSL 1e-6

// f16-derived p has low 13 float bits zero -> key = (bits>>13) - KOFF is lossless
#define KOFF 105472u    // 0x33800000 >> 13  (p = 2^-24, min positive f16)
#define NHB  24576      // keys span [0, 24575] for p in [2^-24, 1)
#define CH   24         // NHB / 1024

// ---------------- scratch (device globals; no runtime allocation) ----------
__device__ unsigned int g_hist1[BATCH][NHB];     // 1.6 MB
__device__ double g_sp[BATCH], g_sp2[BATCH], g_losstext[BATCH];
__device__ unsigned int g_npos[BATCH];
__device__ double g_ki[BATCH * NKC], g_kii[BATCH * NKC], g_ktt[BATCH * NKC];

// ---------------- helpers ----------------
// two sigmoids in one MUFU op: p = 0.5*tanh(x/2)+0.5 on f16x2
__device__ __forceinline__ __half2 htanh2(__half2 v) {
    unsigned u = *reinterpret_cast<unsigned*>(&v);
    unsigned r;
    asm("tanh.approx.f16x2 %0, %1;" : "=r"(r) : "r"(u));
    return *reinterpret_cast<__half2*>(&r);
}
__device__ __forceinline__ __half2 sig2(float x0, float x1) {
    const __half2 h05 = __half2half2(__float2half_rn(0.5f));
    __half2 h = __floats2half2_rn(x0, x1);
    h = __hmul2(h, h05);
    __half2 t = htanh2(h);
    return __hfma2(t, h05, h05);
}

// packed f32x2 ops
__device__ __forceinline__ unsigned long long pack2(float lo, float hi) {
    unsigned long long r;
    asm("mov.b64 %0, {%1, %2};" : "=l"(r) : "f"(lo), "f"(hi));
    return r;
}
__device__ __forceinline__ unsigned long long mul2(unsigned long long a, unsigned long long b) {
    unsigned long long r;
    asm("mul.rn.f32x2 %0, %1, %2;" : "=l"(r) : "l"(a), "l"(b));
    return r;
}
__device__ __forceinline__ unsigned long long fma2(unsigned long long a, unsigned long long b,
                                                   unsigned long long c) {
    unsigned long long r;
    asm("fma.rn.f32x2 %0, %1, %2, %3;" : "=l"(r) : "l"(a), "l"(b), "l"(c));
    return r;
}
__device__ __forceinline__ float hsum2(unsigned long long v) {
    float lo, hi;
    asm("mov.b64 {%0, %1}, %2;" : "=f"(lo), "=f"(hi) : "l"(v));
    return lo + hi;
}

__device__ __forceinline__ float blockReduceF(float v, float* s) {
    #pragma unroll
    for (int o = 16; o; o >>= 1) v += __shfl_down_sync(0xFFFFFFFFu, v, o);
    int lane = threadIdx.x & 31, w = threadIdx.x >> 5;
    if (lane == 0) s[w] = v;
    __syncthreads();
    v = (threadIdx.x < (blockDim.x >> 5)) ? s[threadIdx.x] : 0.0f;
    if (w == 0) {
        #pragma unroll
        for (int o = 4; o; o >>= 1) v += __shfl_down_sync(0xFFFFFFFFu, v, o);
    }
    __syncthreads();
    return v;
}

// ---------------- kernels ----------------
__global__ void zero_kernel() {
    unsigned idx = blockIdx.x * blockDim.x + threadIdx.x;
    unsigned stride = gridDim.x * blockDim.x;
    const unsigned n = BATCH * NHB;
    unsigned* h1 = &g_hist1[0][0];
    for (unsigned i = idx; i < n; i += stride) h1[i] = 0u;
    if (idx < BATCH) {
        g_sp[idx] = 0.0; g_sp2[idx] = 0.0; g_losstext[idx] = 0.0;
        g_npos[idx] = 0u;
    }
    if (idx < BATCH * NKC) { g_ki[idx] = 0.0; g_kii[idx] = 0.0; g_ktt[idx] = 0.0; }
}

// single fused sweep over all data: text sums + exact-key histogram + kernel dice
__global__ void __launch_bounds__(NT) pass1_kernel(
    const float4* __restrict__ pred, const float4* __restrict__ gtt,
    const float4* __restrict__ gtk,  const float4* __restrict__ msk)
{
    __shared__ float sred[8];
    int b = blockIdx.x / PB;
    int base4 = (blockIdx.x % PB) * CHUNK4;

    const float4* m4 = msk + (size_t)b * HW4;
    const float4* g4 = gtt + (size_t)b * HW4;
    const float4* p4 = pred + (size_t)b * 6 * HW4;   // channel 0 = text
    const float4* gk0 = gtk + (size_t)b * NKC * HW4;
    unsigned* __restrict__ h1 = &g_hist1[b][0];

    float sp = 0.f, sp2 = 0.f, np = 0.f;
    // per-channel packed accumulators: [c][0]=inter, [c][1]=sii, [c][2]=stt
    unsigned long long acc[NKC][3];
    #pragma unroll
    for (int c = 0; c < NKC; c++) { acc[c][0] = 0ull; acc[c][1] = 0ull; acc[c][2] = 0ull; }

    #pragma unroll
    for (int i = 0; i < 4; i++) {
        int idx = base4 + threadIdx.x + i * NT;
        float4 mv = m4[idx];
        float4 gv = g4[idx];
        float4 pv = p4[idx];

        // ---- text channel ----
        __half2 tA = sig2(pv.x, pv.y);
        __half2 tB = sig2(pv.z, pv.w);
        float ps0 = __low2float(tA), ps1 = __high2float(tA);
        float ps2 = __low2float(tB), ps3 = __high2float(tB);
        #define PROC(COMP, PV)                                                    \
        {                                                                         \
            float m = mv.COMP, g = gv.COMP;                                       \
            float p = PV;                                                         \
            float pm = g * m;                                                     \
            float pp = p * pm;                                                    \
            np += pm; sp += pp; sp2 = fmaf(pp, pp, sp2);                          \
            if (m - g > 0.5f) {       /* negative: m=1 && g=0 */                  \
                unsigned bits = __float_as_uint(p);                               \
                unsigned key = bits >> 13;                                        \
                key = (key > KOFF) ? key - KOFF : 0u;                             \
                if (key >= NHB) key = NHB - 1u;                                   \
                atomicAdd(&h1[key], 1u);                                          \
            }                                                                     \
        }
        PROC(x, ps0) PROC(y, ps1) PROC(z, ps2) PROC(w, ps3)
        #undef PROC

        // ---- kernel dice channels (m,g in {0,1}) ----
        unsigned long long m01 = pack2(mv.x, mv.y);
        unsigned long long m23 = pack2(mv.z, mv.w);
        #pragma unroll
        for (int c = 0; c < NKC; c++) {
            float4 pk = p4[(size_t)(1 + c) * HW4 + idx];
            float4 gk = gk0[(size_t)c * HW4 + idx];
            __half2 sA = sig2(pk.x, pk.y);
            __half2 sB = sig2(pk.z, pk.w);
            unsigned long long s01 = pack2(__low2float(sA), __high2float(sA));
            unsigned long long s23 = pack2(__low2float(sB), __high2float(sB));
            unsigned long long g01 = pack2(gk.x, gk.y);
            unsigned long long g23 = pack2(gk.z, gk.w);
            unsigned long long sm01 = mul2(s01, m01);
            unsigned long long sm23 = mul2(s23, m23);
            acc[c][0] = fma2(sm01, g01, fma2(sm23, g23, acc[c][0]));  // s*g*m
            acc[c][1] = fma2(sm01, s01, fma2(sm23, s23, acc[c][1]));  // s*s*m
            acc[c][2] = fma2(g01, m01, fma2(g23, m23, acc[c][2]));    // g*m
        }
    }

    float t;
    t = blockReduceF(sp,  sred); if (threadIdx.x == 0) atomicAdd(&g_sp[b],  (double)t);
    t = blockReduceF(sp2, sred); if (threadIdx.x == 0) atomicAdd(&g_sp2[b], (double)t);
    t = blockReduceF(np,  sred); if (threadIdx.x == 0) atomicAdd(&g_npos[b], (unsigned)(t + 0.5f));

    #pragma unroll
    for (int c = 0; c < NKC; c++) {
        int id = b * NKC + c;
        float r;
        r = blockReduceF(hsum2(acc[c][0]), sred);
        if (threadIdx.x == 0) atomicAdd(&g_ki[id],  (double)r);
        r = blockReduceF(hsum2(acc[c][1]), sred);
        if (threadIdx.x == 0) atomicAdd(&g_kii[id], (double)r);
        r = blockReduceF(hsum2(acc[c][2]), sred);
        if (threadIdx.x == 0) atomicAdd(&g_ktt[id], (double)r);
    }
}

// per-batch: OHEM select over exact-key histogram + hard-negative sum + loss_text
__global__ void __launch_bounds__(1024) pass2_kernel() {
    int b = blockIdx.x;
    int t = threadIdx.x;
    __shared__ unsigned ccnt[1024];   // -> inclusive suffix counts
    __shared__ double   cw[1024];     // -> inclusive suffix of count*v^2
    __shared__ double   sHard;

    int base = t * CH;
    unsigned s = 0; double w = 0.0;
    #pragma unroll 4
    for (int j = 0; j < CH; j++) {
        unsigned c = g_hist1[b][base + j];
        if (c) {
            float v = __uint_as_float((unsigned)(base + j) + KOFF << 13);
            s += c; w += (double)c * (double)v * (double)v;
        }
    }
    ccnt[t] = s; cw[t] = w;
    __syncthreads();
    // inclusive suffix scan (Hillis-Steele)
    for (int off = 1; off < 1024; off <<= 1) {
        unsigned ca = (t + off < 1024) ? ccnt[t + off] : 0u;
        double   wa = (t + off < 1024) ? cw[t + off]   : 0.0;
        __syncthreads();
        ccnt[t] += ca; cw[t] += wa;
        __syncthreads();
    }
    unsigned nneg = ccnt[0];
    unsigned npos = g_npos[b];
    unsigned k = 3u * npos; if (k > nneg) k = nneg;
    if (t == 0) sHard = 0.0;
    __syncthreads();
    if (k > 0) {
        unsigned incl  = ccnt[t];
        unsigned above = (t < 1023) ? ccnt[t + 1] : 0u;
        if (above < k && incl >= k) {
            double wacc = (t < 1023) ? cw[t + 1] : 0.0;
            unsigned cum = above;
            for (int j = CH - 1; j >= 0; j--) {
                unsigned c = g_hist1[b][base + j];
                if (!c) continue;
                float v = __uint_as_float((unsigned)(base + j) + KOFF << 13);
                double v2 = (double)v * (double)v;
                if (cum + c >= k) { sHard = wacc + (double)(k - cum) * v2; break; }
                cum += c; wacc += (double)c * v2;
            }
        }
    }
    __syncthreads();
    if (t == 0) {
        double np = (double)npos;
        g_losstext[b] = 1.0 - 2.0 * g_sp[b] / (g_sp2[b] + sHard + np + EPSL);
    }
}

__global__ void final_kernel(float* out) {
    if (threadIdx.x == 0) {
        double lk = 0.0;
        for (int i = 0; i < BATCH * NKC; i++)
            lk += 1.0 - 2.0 * g_ki[i] / (g_kii[i] + g_ktt[i] + EPSL);
        lk /= (double)(BATCH * NKC);
        double lt = 0.0;
        for (int bb = 0; bb < BATCH; bb++) lt += g_losstext[bb];
        lt /= (double)BATCH;
        out[0] = (float)(lk + 0.5 * lt);
        out[1] = (float)lt;
        out[2] = (float)lk;
    }
}

// ---------------- launch ----------------
extern "C" void kernel_launch(void* const* d_in, const int* in_sizes, int n_in,
                              void* d_out, int out_size) {
    const float4* pred = (const float4*)d_in[0];
    const float4* gtt  = (const float4*)d_in[1];
    const float4* gtk  = (const float4*)d_in[2];
    const float4* msk  = (const float4*)d_in[3];
    float* out = (float*)d_out;

    zero_kernel<<<512, 1024>>>();
    pass1_kernel<<<BATCH * PB, NT>>>(pred, gtt, gtk, msk);
    pass2_kernel<<<BATCH, 1024>>>();
    final_kernel<<<1, 32>>>(out);
}

// round 8
// speedup vs baseline: 3.3989x; 1.3212x over previous
#include <cuda_runtime.h>
#include <cuda_fp16.h>
#include <cuda_bf16.h>
#include <cstdint>

#define BATCH 16
#define HW 409600
#define HW4 102400
#define PB 100          // blocks per batch in pass1
#define CHUNK4 1024     // float4 elems per block
#define NT 256
#define NKC 5
#define EPSL 1e-6

// f16-derived p has low 13 float bits zero -> key = (bits>>13) - KOFF is lossless
#define KOFF 105472u    // 0x33800000 >> 13  (p = 2^-24, min positive f16)
#define NHB  24576      // keys span [0, 24575] for p in [2^-24, 1)
#define CH   24         // NHB / 1024

// ---------------- scratch (device globals; no runtime allocation) ----------
__device__ unsigned int g_hist1[BATCH][NHB];     // 1.6 MB
__device__ double g_sp[BATCH], g_sp2[BATCH], g_losstext[BATCH];
__device__ unsigned int g_npos[BATCH];
__device__ double g_ki[BATCH * NKC], g_kii[BATCH * NKC], g_ktt[BATCH * NKC];

// ---------------- helpers ----------------
// two sigmoids in one MUFU op: p = 0.5*tanh(x/2)+0.5 on f16x2
__device__ __forceinline__ __half2 htanh2(__half2 v) {
    unsigned u = *reinterpret_cast<unsigned*>(&v);
    unsigned r;
    asm("tanh.approx.f16x2 %0, %1;" : "=r"(r) : "r"(u));
    return *reinterpret_cast<__half2*>(&r);
}
__device__ __forceinline__ __half2 sig2(float x0, float x1) {
    const __half2 h05 = __half2half2(__float2half_rn(0.5f));
    __half2 h = __floats2half2_rn(x0, x1);
    h = __hmul2(h, h05);
    __half2 t = htanh2(h);
    return __hfma2(t, h05, h05);
}

__device__ __forceinline__ float blockReduceF(float v, float* s) {
    #pragma unroll
    for (int o = 16; o; o >>= 1) v += __shfl_down_sync(0xFFFFFFFFu, v, o);
    int lane = threadIdx.x & 31, w = threadIdx.x >> 5;
    if (lane == 0) s[w] = v;
    __syncthreads();
    v = (threadIdx.x < (blockDim.x >> 5)) ? s[threadIdx.x] : 0.0f;
    if (w == 0) {
        #pragma unroll
        for (int o = 4; o; o >>= 1) v += __shfl_down_sync(0xFFFFFFFFu, v, o);
    }
    __syncthreads();
    return v;
}

// ---------------- kernels ----------------
__global__ void zero_kernel() {
    unsigned idx = blockIdx.x * blockDim.x + threadIdx.x;
    unsigned stride = gridDim.x * blockDim.x;
    const unsigned n = BATCH * NHB;
    unsigned* h1 = &g_hist1[0][0];
    for (unsigned i = idx; i < n; i += stride) h1[i] = 0u;
    if (idx < BATCH) {
        g_sp[idx] = 0.0; g_sp2[idx] = 0.0; g_losstext[idx] = 0.0;
        g_npos[idx] = 0u;
    }
    if (idx < BATCH * NKC) { g_ki[idx] = 0.0; g_kii[idx] = 0.0; g_ktt[idx] = 0.0; }
}

// single fused sweep: text sums + exact-key histogram + kernel dice (all-half2)
__global__ void __launch_bounds__(NT) pass1_kernel(
    const float4* __restrict__ pred, const float4* __restrict__ gtt,
    const float4* __restrict__ gtk,  const float4* __restrict__ msk)
{
    __shared__ float sred[8];
    int b = blockIdx.x / PB;
    int base4 = (blockIdx.x % PB) * CHUNK4;

    const float4* m4 = msk + (size_t)b * HW4;
    const float4* g4 = gtt + (size_t)b * HW4;
    const float4* p4 = pred + (size_t)b * 6 * HW4;   // channel 0 = text
    const float4* gk0 = gtk + (size_t)b * NKC * HW4;
    unsigned* __restrict__ h1 = &g_hist1[b][0];

    float sp = 0.f, sp2 = 0.f, np = 0.f;
    // half2 accumulators; per-thread slot sums <= 32 (16 px/thread/channel)
    __half2 aint[NKC], asii[NKC], astt[NKC];
    const __half2 hz = __half2half2(__float2half_rn(0.0f));
    #pragma unroll
    for (int c = 0; c < NKC; c++) { aint[c] = hz; asii[c] = hz; astt[c] = hz; }

    #pragma unroll
    for (int i = 0; i < 4; i++) {
        int idx = base4 + threadIdx.x + i * NT;
        float4 mv = m4[idx];
        float4 gv = g4[idx];
        float4 pv = p4[idx];

        // ---- text channel (f32 path: feeds selection + dice numerator) ----
        __half2 tA = sig2(pv.x, pv.y);
        __half2 tB = sig2(pv.z, pv.w);
        float ps0 = __low2float(tA), ps1 = __high2float(tA);
        float ps2 = __low2float(tB), ps3 = __high2float(tB);
        #define PROC(COMP, PV)                                                    \
        {                                                                         \
            float m = mv.COMP, g = gv.COMP;                                       \
            float p = PV;                                                         \
            float pm = g * m;                                                     \
            float pp = p * pm;                                                    \
            np += pm; sp += pp; sp2 = fmaf(pp, pp, sp2);                          \
            if (m - g > 0.5f) {       /* negative: m=1 && g=0 */                  \
                unsigned bits = __float_as_uint(p);                               \
                unsigned key = bits >> 13;                                        \
                key = (key > KOFF) ? key - KOFF : 0u;                             \
                if (key >= NHB) key = NHB - 1u;                                   \
                atomicAdd(&h1[key], 1u);                                          \
            }                                                                     \
        }
        PROC(x, ps0) PROC(y, ps1) PROC(z, ps2) PROC(w, ps3)
        #undef PROC

        // ---- kernel dice channels, all half2 (m,g in {0,1}) ----
        __half2 mh01 = __floats2half2_rn(mv.x, mv.y);
        __half2 mh23 = __floats2half2_rn(mv.z, mv.w);
        #pragma unroll
        for (int c = 0; c < NKC; c++) {
            float4 pk = p4[(size_t)(1 + c) * HW4 + idx];
            float4 gk = gk0[(size_t)c * HW4 + idx];
            __half2 sA = sig2(pk.x, pk.y);
            __half2 sB = sig2(pk.z, pk.w);
            __half2 gA = __floats2half2_rn(gk.x, gk.y);
            __half2 gB = __floats2half2_rn(gk.z, gk.w);
            __half2 smA = __hmul2(sA, mh01);
            __half2 smB = __hmul2(sB, mh23);
            aint[c] = __hfma2(smA, gA, __hfma2(smB, gB, aint[c]));  // s*g*m
            asii[c] = __hfma2(smA, sA, __hfma2(smB, sB, asii[c]));  // s*s*m
            astt[c] = __hfma2(gA, mh01, __hfma2(gB, mh23, astt[c])); // g*m (exact)
        }
    }

    float t;
    t = blockReduceF(sp,  sred); if (threadIdx.x == 0) atomicAdd(&g_sp[b],  (double)t);
    t = blockReduceF(sp2, sred); if (threadIdx.x == 0) atomicAdd(&g_sp2[b], (double)t);
    t = blockReduceF(np,  sred); if (threadIdx.x == 0) atomicAdd(&g_npos[b], (unsigned)(t + 0.5f));

    #pragma unroll
    for (int c = 0; c < NKC; c++) {
        int id = b * NKC + c;
        float r;
        r = blockReduceF(__low2float(aint[c]) + __high2float(aint[c]), sred);
        if (threadIdx.x == 0) atomicAdd(&g_ki[id],  (double)r);
        r = blockReduceF(__low2float(asii[c]) + __high2float(asii[c]), sred);
        if (threadIdx.x == 0) atomicAdd(&g_kii[id], (double)r);
        r = blockReduceF(__low2float(astt[c]) + __high2float(astt[c]), sred);
        if (threadIdx.x == 0) atomicAdd(&g_ktt[id], (double)r);
    }
}

// per-batch: OHEM select over exact-key histogram + hard-negative sum + loss_text
__global__ void __launch_bounds__(1024) pass2_kernel() {
    int b = blockIdx.x;
    int t = threadIdx.x;
    __shared__ unsigned ccnt[1024];   // -> inclusive suffix counts
    __shared__ double   cw[1024];     // -> inclusive suffix of count*v^2
    __shared__ double   sHard;

    int base = t * CH;
    unsigned s = 0; double w = 0.0;
    #pragma unroll 4
    for (int j = 0; j < CH; j++) {
        unsigned c = g_hist1[b][base + j];
        if (c) {
            float v = __uint_as_float((unsigned)(base + j) + KOFF << 13);
            s += c; w += (double)c * (double)v * (double)v;
        }
    }
    ccnt[t] = s; cw[t] = w;
    __syncthreads();
    // inclusive suffix scan (Hillis-Steele)
    for (int off = 1; off < 1024; off <<= 1) {
        unsigned ca = (t + off < 1024) ? ccnt[t + off] : 0u;
        double   wa = (t + off < 1024) ? cw[t + off]   : 0.0;
        __syncthreads();
        ccnt[t] += ca; cw[t] += wa;
        __syncthreads();
    }
    unsigned nneg = ccnt[0];
    unsigned npos = g_npos[b];
    unsigned k = 3u * npos; if (k > nneg) k = nneg;
    if (t == 0) sHard = 0.0;
    __syncthreads();
    if (k > 0) {
        unsigned incl  = ccnt[t];
        unsigned above = (t < 1023) ? ccnt[t + 1] : 0u;
        if (above < k && incl >= k) {
            double wacc = (t < 1023) ? cw[t + 1] : 0.0;
            unsigned cum = above;
            for (int j = CH - 1; j >= 0; j--) {
                unsigned c = g_hist1[b][base + j];
                if (!c) continue;
                float v = __uint_as_float((unsigned)(base + j) + KOFF << 13);
                double v2 = (double)v * (double)v;
                if (cum + c >= k) { sHard = wacc + (double)(k - cum) * v2; break; }
                cum += c; wacc += (double)c * v2;
            }
        }
    }
    __syncthreads();
    if (t == 0) {
        double np = (double)npos;
        g_losstext[b] = 1.0 - 2.0 * g_sp[b] / (g_sp2[b] + sHard + np + EPSL);
    }
}

// parallel epilogue: one (b,c) dice term per thread, tree reduce
__global__ void __launch_bounds__(128) final_kernel(float* out) {
    __shared__ double sd[128];
    int t = threadIdx.x;
    double v = 0.0;
    if (t < BATCH * NKC)
        v = 1.0 - 2.0 * g_ki[t] / (g_kii[t] + g_ktt[t] + EPSL);
    sd[t] = v;
    __syncthreads();
    #pragma unroll
    for (int o = 64; o; o >>= 1) { if (t < o) sd[t] += sd[t + o]; __syncthreads(); }
    double lk = sd[0] / (double)(BATCH * NKC);
    __syncthreads();
    sd[t] = (t < BATCH) ? g_losstext[t] : 0.0;
    __syncthreads();
    #pragma unroll
    for (int o = 64; o; o >>= 1) { if (t < o) sd[t] += sd[t + o]; __syncthreads(); }
    if (t == 0) {
        double lt = sd[0] / (double)BATCH;
        out[0] = (float)(lk + 0.5 * lt);
        out[1] = (float)lt;
        out[2] = (float)lk;
    }
}

// ---------------- launch ----------------
extern "C" void kernel_launch(void* const* d_in, const int* in_sizes, int n_in,
                              void* d_out, int out_size) {
    const float4* pred = (const float4*)d_in[0];
    const float4* gtt  = (const float4*)d_in[1];
    const float4* gtk  = (const float4*)d_in[2];
    const float4* msk  = (const float4*)d_in[3];
    float* out = (float*)d_out;

    zero_kernel<<<512, 1024>>>();
    pass1_kernel<<<BATCH * PB, NT>>>(pred, gtt, gtk, msk);
    pass2_kernel<<<BATCH, 1024>>>();
    final_kernel<<<1, 128>>>(out);
}